// round 16
// baseline (speedup 1.0000x reference)
#include <cuda_runtime.h>
#include <cuda_fp16.h>
#include <cstdint>

#define HID   256
#define H2    128
#define NMAX  (1 << 20)
#define GMAX  4096

// Scratch (no device allocation allowed -> __device__ globals)
__device__ float g_scores[NMAX];
__device__ int   g_gstart[GMAX + 1];
__device__ int   g_batch_is64;

// ===========================================================================
// Helpers
// ===========================================================================
__device__ __forceinline__ uint32_t smem_u32(const void* p) {
    uint32_t a;
    asm("{ .reg .u64 t; cvta.to.shared.u64 t, %1; cvt.u32.u64 %0, t; }" : "=r"(a) : "l"(p));
    return a;
}
#define SWZ128(o) ((o) ^ (((o) >> 3) & 0x70))

__device__ __forceinline__ void ldsm4(uint32_t* r, uint32_t addr) {
    asm volatile("ldmatrix.sync.aligned.m8n8.x4.shared.b16 {%0,%1,%2,%3}, [%4];"
                 : "=r"(r[0]), "=r"(r[1]), "=r"(r[2]), "=r"(r[3]) : "r"(addr));
}
__device__ __forceinline__ void mma16816(float* d, const uint32_t* a,
                                         uint32_t b0, uint32_t b1) {
    asm volatile("mma.sync.aligned.m16n8k16.row.col.f32.f16.f16.f32 "
                 "{%0,%1,%2,%3}, {%4,%5,%6,%7}, {%8,%9}, {%0,%1,%2,%3};"
                 : "+f"(d[0]), "+f"(d[1]), "+f"(d[2]), "+f"(d[3])
                 : "r"(a[0]), "r"(a[1]), "r"(a[2]), "r"(a[3]), "r"(b0), "r"(b1));
}
__device__ __forceinline__ float tanh_hw(float z) {
    float r;
    asm("tanh.approx.f32 %0, %1;" : "=f"(r) : "f"(z));
    return r;
}
__device__ __forceinline__ void cp_async16(uint32_t saddr, const void* gptr) {
    asm volatile("cp.async.cg.shared.global [%0], [%1], 16;"
                 :: "r"(saddr), "l"(gptr) : "memory");
}
#define CP_COMMIT()  asm volatile("cp.async.commit_group;" ::: "memory")
#define CP_WAIT1()   asm volatile("cp.async.wait_group 1;" ::: "memory")

// ===========================================================================
// SMEM layout (bytes)
//   bw:   float2[128]  (b1, W2) pairs
//   W:    4 panels of [128 n][64 k] fp16 SW128 (16KB each) = 64KB
//   A:    2 buffers x 16KB (x tile as fp16, [128 row][64 k], SW128)
//   RING: 3 slots x 32KB raw fp32 quarter tiles ([128 row][16 float4])
//   SRED: float[128][5] cross-warp_n score reduction
// ===========================================================================
#define SM_BW     0
#define SM_B2     1024
#define SM_W      2048
#define SM_A      (SM_W + 65536)            // 67584
#define SM_RING   (SM_A + 2 * 16384)        // 100352
#define SM_SRED   (SM_RING + 3 * 32768)     // 198656
#define SM_TOTAL  (SM_SRED + 128 * 5 * 4)   // 201216

// ===========================================================================
// Pass A: scores = tanh(x@W1 + b1) @ W2 + b2, warp-MMA pure fp16.
//   Persistent 1 CTA/SM, 256 threads (8 warps in 2x4 grid: m64 x n32 each).
//   Tile = 128 nodes x 128 hidden. K=256 in 4 quarters of 64.
//   x streamed GMEM->SMEM via cp.async ring (depth 3, issued 2 quarters
//   ahead) -> no LDG->register dependency, no exposed DRAM latency.
// ===========================================================================
__global__ __launch_bounds__(256, 1)
void scores_mma_kernel(const float* __restrict__ x,
                       const float* __restrict__ W1,
                       const float* __restrict__ b1,
                       const float* __restrict__ W2,
                       const float* __restrict__ b2,
                       int N, int numTiles)
{
    extern __shared__ char smem[];
    const uint32_t sb = smem_u32(smem);
    const int tid  = threadIdx.x;
    const int wid  = tid >> 5;
    const int lane = tid & 31;
    const int warp_m = wid >> 2;       // 0..1  -> rows warp_m*64 .. +63
    const int warp_n = wid & 3;        // 0..3  -> cols warp_n*32 .. +31

    // Stage W1^T -> fp16 SW128 panels [n][k-quarter]
    for (int idx = tid; idx < HID * H2; idx += 256) {
        int k = idx >> 7;          // 0..255
        int n = idx & 127;         // 0..127
        __half h = __float2half_rn(W1[idx]);
        uint32_t sw = SWZ128((uint32_t)n * 128u + (uint32_t)(k & 63) * 2u);
        int p = k >> 6;
        *(__half*)(smem + SM_W + p * 16384 + sw) = h;
    }
    if (tid < 128) ((float2*)(smem + SM_BW))[tid] = make_float2(b1[tid], W2[tid]);
    if (tid == 0)  ((float*)(smem + SM_B2))[0] = b2[0];
    __syncthreads();

    const float bias2 = ((float*)(smem + SM_B2))[0];
    const float2* bw  = (const float2*)(smem + SM_BW);
    float* sred       = (float*)(smem + SM_SRED);

    // Per-lane ldmatrix address components
    const int amat = lane >> 3;                          // 0..3
    const int arow0 = warp_m * 64 + ((amat & 1) << 3) + (lane & 7);  // mb adds 16
    const uint32_t aoff0 = (uint32_t)arow0 * 128u;
    const uint32_t axor  = (uint32_t)(lane & 7) << 4;
    const uint32_t amk   = (uint32_t)(amat >> 1) << 4;

    const int bmat = lane >> 3;
    const uint32_t browb = (uint32_t)(warp_n * 32 + ((bmat >> 1) << 3) + (lane & 7)) * 128u; // nbp adds 16 rows
    const uint32_t bxor  = (uint32_t)(lane & 7) << 4;
    const uint32_t bmk   = (uint32_t)(bmat & 1) << 4;

    const float4* x4 = (const float4*)x;

    if (blockIdx.x >= numTiles) return;

    // cp.async issue for CTA-local quarter qg (tile = blockIdx.x + (qg/4)*grid)
    auto issue_quarter = [&](int qg) {
        int tile = blockIdx.x + (qg >> 2) * (int)gridDim.x;
        if (tile < numTiles) {
            const int base = tile * 128;
            const int q = qg & 3;
            const uint32_t ring = sb + SM_RING + (uint32_t)(qg % 3) * 32768u;
#pragma unroll
            for (int it = 0; it < 8; it++) {
                int f = (it << 8) + tid;
                int row = f >> 4, c4 = f & 15;
                int gn = base + row; if (gn >= N) gn = N - 1;
                cp_async16(ring + (uint32_t)f * 16u,
                           (const void*)(x4 + (size_t)gn * 64 + q * 16 + c4));
            }
        }
        CP_COMMIT();
    };

    issue_quarter(0);
    issue_quarter(1);

    int qg = 0;
    for (int t = blockIdx.x; t < numTiles; t += gridDim.x) {
        const int base = t * 128;
        float d[4][4][4];   // [mb m16][nb n8][frag]
#pragma unroll
        for (int i = 0; i < 4; i++)
#pragma unroll
            for (int j = 0; j < 4; j++)
#pragma unroll
                for (int kreg = 0; kreg < 4; kreg++) d[i][j][kreg] = 0.0f;

        for (int q = 0; q < 4; q++, qg++) {
            const uint32_t abase = sb + SM_A + (uint32_t)(qg & 1) * 16384u;
            const uint32_t ring  = sb + SM_RING + (uint32_t)(qg % 3) * 32768u;

            CP_WAIT1();        // quarter qg arrived (qg+1 may be in flight)
            __syncthreads();   // bar A: arrival visible to all; fp16 buf free

            // stage: LDS raw fp32 -> CVT -> STS fp16 (SW128)
#pragma unroll
            for (int it = 0; it < 8; it++) {
                int f = (it << 8) + tid;
                int row = f >> 4, c4 = f & 15;
                float4 w = *(const float4*)(smem + (ring - sb) + (uint32_t)f * 16u);
                __half2 h0 = __float22half2_rn(make_float2(w.x, w.y));
                __half2 h1 = __float22half2_rn(make_float2(w.z, w.w));
                uint32_t sw = SWZ128((uint32_t)row * 128u + (uint32_t)c4 * 8u);
                uint2 hv;
                hv.x = *(uint32_t*)&h0; hv.y = *(uint32_t*)&h1;
                *(uint2*)(smem + (abase - sb) + sw) = hv;
            }
            __syncthreads();   // bar B: fp16 buf complete; ring slot consumed

            issue_quarter(qg + 2);   // refill slot (qg-1)%3, 2 quarters ahead

            // compute: 4 k-steps of 16 over this quarter
            const uint32_t wbase = sb + SM_W + (uint32_t)q * 16384u;
#pragma unroll
            for (int ks = 0; ks < 4; ks++) {
                const uint32_t kk = (uint32_t)ks * 32u;
                const uint32_t aterm = (kk + amk) ^ axor;
                const uint32_t bterm = (kk + bmk) ^ bxor;
                uint32_t ah[4][4];
#pragma unroll
                for (int mb = 0; mb < 4; mb++)
                    ldsm4(ah[mb], abase + aoff0 + (uint32_t)mb * 2048u + aterm);
#pragma unroll
                for (int nbp = 0; nbp < 2; nbp++) {
                    uint32_t bh[4];
                    ldsm4(bh, wbase + (uint32_t)nbp * 2048u + browb + bterm);
#pragma unroll
                    for (int mb = 0; mb < 4; mb++) {
                        mma16816(d[mb][nbp * 2],     ah[mb], bh[0], bh[1]);
                        mma16816(d[mb][nbp * 2 + 1], ah[mb], bh[2], bh[3]);
                    }
                }
            }
        }

        // Epilogue: lane covers rows {r0, r0+8} per mb, cols warp_n*32+nb*8+2*(lane%4)+j
        const int cbase = warp_n * 32 + 2 * (lane & 3);
#pragma unroll
        for (int mb = 0; mb < 4; mb++) {
            float s0 = 0.0f, s1 = 0.0f;
#pragma unroll
            for (int nb = 0; nb < 4; nb++) {
#pragma unroll
                for (int j = 0; j < 2; j++) {
                    float2 bwv = bw[cbase + nb * 8 + j];
                    s0 = fmaf(tanh_hw(d[mb][nb][j]     + bwv.x), bwv.y, s0);
                    s1 = fmaf(tanh_hw(d[mb][nb][2 + j] + bwv.x), bwv.y, s1);
                }
            }
            s0 += __shfl_xor_sync(0xffffffffu, s0, 1);
            s0 += __shfl_xor_sync(0xffffffffu, s0, 2);
            s1 += __shfl_xor_sync(0xffffffffu, s1, 1);
            s1 += __shfl_xor_sync(0xffffffffu, s1, 2);
            if ((lane & 3) == 0) {
                int r0 = warp_m * 64 + mb * 16 + (lane >> 2);
                sred[r0 * 5 + warp_n]       = s0;
                sred[(r0 + 8) * 5 + warp_n] = s1;
            }
        }
        __syncthreads();
        if (tid < 128) {
            int gn = base + tid;
            if (gn < N) {
                float s = (sred[tid * 5 + 0] + sred[tid * 5 + 1]) +
                          (sred[tid * 5 + 2] + sred[tid * 5 + 3]);
                g_scores[gn] = s + bias2;
            }
        }
    }
}

// ---------------------------------------------------------------------------
// Batch dtype probe (JAX demotes int64->int32 unless x64 enabled)
// ---------------------------------------------------------------------------
__global__ void detect_kernel(const int* __restrict__ b32, int N)
{
    bool is64 = true;
    int checked = 0;
    for (int i = 1; i < 256 && checked < 16; i++) {
        int idx = N - i;
        if (idx < 1) break;
        if (idx & 1) {
            checked++;
            if (b32[idx] != 0) { is64 = false; break; }
        }
    }
    g_batch_is64 = is64 ? 1 : 0;
}

// ---------------------------------------------------------------------------
// Graph range offsets: batch sorted -> per-graph lower_bound
// ---------------------------------------------------------------------------
__global__ void offsets_kernel(const void* __restrict__ batch, int N, int G)
{
    int g = blockIdx.x * blockDim.x + threadIdx.x;
    if (g > G) return;
    if (g == G) { g_gstart[G] = N; return; }
    const int is64 = g_batch_is64;
    const long long* b64 = (const long long*)batch;
    const int*       b32 = (const int*)batch;
    int lo = 0, hi = N;
    while (lo < hi) {
        int mid = (lo + hi) >> 1;
        long long v = is64 ? b64[mid] : (long long)b32[mid];
        if (v < (long long)g) lo = mid + 1; else hi = mid;
    }
    g_gstart[g] = lo;
}

// ---------------------------------------------------------------------------
// Pass B+C fused: per-graph segment softmax + weighted feature sum (float4).
// ---------------------------------------------------------------------------
#define CHUNK 1024
__global__ __launch_bounds__(256)
void pool_kernel(const float4* __restrict__ x4, float4* __restrict__ out4)
{
    const int g   = blockIdx.x;
    const int tid = threadIdx.x;
    const int s = g_gstart[g], e = g_gstart[g + 1];

    __shared__ float  red[256];
    __shared__ float  wbuf[CHUNK];
    __shared__ float4 red4[256];

    // phase 1: segment max
    float m = -3.0e38f;
    for (int i = s + tid; i < e; i += 256) m = fmaxf(m, g_scores[i]);
    red[tid] = m; __syncthreads();
#pragma unroll
    for (int o = 128; o > 0; o >>= 1) {
        if (tid < o) red[tid] = fmaxf(red[tid], red[tid + o]);
        __syncthreads();
    }
    m = red[0]; __syncthreads();

    // phase 2: denom
    float dsum = 0.0f;
    for (int i = s + tid; i < e; i += 256) dsum += __expf(g_scores[i] - m);
    red[tid] = dsum; __syncthreads();
#pragma unroll
    for (int o = 128; o > 0; o >>= 1) {
        if (tid < o) red[tid] += red[tid + o];
        __syncthreads();
    }
    float inv = (e > s) ? (1.0f / red[0]) : 0.0f;
    __syncthreads();

    // phase 3: weighted sum, float4 per thread, 4 node groups
    const int c  = tid & 63;
    const int gr = tid >> 6;
    float4 acc = make_float4(0.f, 0.f, 0.f, 0.f);
    for (int cs = s; cs < e; cs += CHUNK) {
        int ce = min(e, cs + CHUNK);
        for (int i = cs + tid; i < ce; i += 256)
            wbuf[i - cs] = __expf(g_scores[i] - m) * inv;
        __syncthreads();
        int cnt = ce - cs;
#pragma unroll 2
        for (int i = gr; i < cnt; i += 4) {
            float w = wbuf[i];
            float4 vv = x4[(size_t)(cs + i) * 64 + c];
            acc.x = fmaf(vv.x, w, acc.x);
            acc.y = fmaf(vv.y, w, acc.y);
            acc.z = fmaf(vv.z, w, acc.z);
            acc.w = fmaf(vv.w, w, acc.w);
        }
        __syncthreads();
    }
    red4[tid] = acc;
    __syncthreads();
    if (tid < 64) {
        float4 a = red4[tid], b = red4[tid + 64], cc = red4[tid + 128], dd = red4[tid + 192];
        float4 r;
        r.x = (a.x + b.x) + (cc.x + dd.x);
        r.y = (a.y + b.y) + (cc.y + dd.y);
        r.z = (a.z + b.z) + (cc.z + dd.z);
        r.w = (a.w + b.w) + (cc.w + dd.w);
        out4[(size_t)g * 64 + tid] = r;
    }
}

// ---------------------------------------------------------------------------
extern "C" void kernel_launch(void* const* d_in, const int* in_sizes, int n_in,
                              void* d_out, int out_size)
{
    const float* x     = (const float*)d_in[0];
    const void*  batch = d_in[1];
    const float* W1    = (const float*)d_in[2];
    const float* b1    = (const float*)d_in[3];
    const float* W2    = (const float*)d_in[4];
    const float* b2    = (const float*)d_in[5];

    const int N = in_sizes[0] / HID;
    const int G = out_size / HID;
    const int numTiles = (N + 127) / 128;

    int dev = 0;
    cudaGetDevice(&dev);
    int sms = 148;
    if (cudaDeviceGetAttribute(&sms, cudaDevAttrMultiProcessorCount, dev) != cudaSuccess || sms <= 0)
        sms = 148;

    cudaFuncSetAttribute(scores_mma_kernel,
                         cudaFuncAttributeMaxDynamicSharedMemorySize, SM_TOTAL);

    detect_kernel<<<1, 1>>>((const int*)batch, N);
    offsets_kernel<<<(G + 1 + 255) / 256, 256>>>(batch, N, G);

    int grid = sms < numTiles ? sms : numTiles;
    scores_mma_kernel<<<grid, 256, SM_TOTAL>>>(x, W1, b1, W2, b2, N, numTiles);
    pool_kernel<<<G, 256>>>((const float4*)x, (float4*)d_out);
}

// round 17
// speedup vs baseline: 1.0504x; 1.0504x over previous
#include <cuda_runtime.h>
#include <cuda_fp16.h>
#include <cstdint>

#define HID   256
#define H2    128
#define NMAX  (1 << 20)
#define GMAX  4096

// Scratch (no device allocation allowed -> __device__ globals)
__device__ float g_scores[NMAX];
__device__ int   g_gstart[GMAX + 1];
__device__ int   g_batch_is64;

// ===========================================================================
// Helpers
// ===========================================================================
__device__ __forceinline__ uint32_t smem_u32(const void* p) {
    uint32_t a;
    asm("{ .reg .u64 t; cvta.to.shared.u64 t, %1; cvt.u32.u64 %0, t; }" : "=r"(a) : "l"(p));
    return a;
}
#define SWZ128(o) ((o) ^ (((o) >> 3) & 0x70))

__device__ __forceinline__ void ldsm4(uint32_t* r, uint32_t addr) {
    asm volatile("ldmatrix.sync.aligned.m8n8.x4.shared.b16 {%0,%1,%2,%3}, [%4];"
                 : "=r"(r[0]), "=r"(r[1]), "=r"(r[2]), "=r"(r[3]) : "r"(addr));
}
__device__ __forceinline__ void mma16816(float* d, const uint32_t* a,
                                         uint32_t b0, uint32_t b1) {
    asm volatile("mma.sync.aligned.m16n8k16.row.col.f32.f16.f16.f32 "
                 "{%0,%1,%2,%3}, {%4,%5,%6,%7}, {%8,%9}, {%0,%1,%2,%3};"
                 : "+f"(d[0]), "+f"(d[1]), "+f"(d[2]), "+f"(d[3])
                 : "r"(a[0]), "r"(a[1]), "r"(a[2]), "r"(a[3]), "r"(b0), "r"(b1));
}
__device__ __forceinline__ float tanh_hw(float z) {
    float r;
    asm("tanh.approx.f32 %0, %1;" : "=f"(r) : "f"(z));
    return r;
}

// ===========================================================================
// SMEM layout (bytes)
//   bw:   float2[128]  (b1, W2) pairs
//   W:    4 panels of [128 n][64 k] fp16 SW128 (16KB each) = 64KB
//   A:    2 buffers x 16KB (x tile as fp16, [128 row][64 k], SW128)
//   SRED: float[128][5] cross-warp_n score reduction
// ===========================================================================
#define SM_BW     0
#define SM_B2     1024
#define SM_W      2048
#define SM_A      (SM_W + 65536)           // 67584, 1024-aligned
#define SM_SRED   (SM_A + 2 * 16384)       // 100352
#define SM_TOTAL  (SM_SRED + 128 * 5 * 4)  // 102912

// ===========================================================================
// Pass A: scores = tanh(x@W1 + b1) @ W2 + b2, warp-MMA pure fp16.
//   Persistent 1 CTA/SM, 512 threads (16 warps in 4x4 grid: m32 x n32 each)
//   -> 4 warps/SMSP to hide staging/ldsm/LDG latency in the HMMA stream.
//   Tile = 128 nodes x 128 hidden. K=256 in 4 quarters of 64,
//   register-prefetch double buffer (R9 scheme).
// ===========================================================================
__global__ __launch_bounds__(512, 1)
void scores_mma_kernel(const float* __restrict__ x,
                       const float* __restrict__ W1,
                       const float* __restrict__ b1,
                       const float* __restrict__ W2,
                       const float* __restrict__ b2,
                       int N, int numTiles)
{
    extern __shared__ char smem[];
    const uint32_t sb = smem_u32(smem);
    const int tid  = threadIdx.x;
    const int wid  = tid >> 5;
    const int lane = tid & 31;
    const int warp_m = wid >> 2;       // 0..3  -> rows warp_m*32 .. +31
    const int warp_n = wid & 3;        // 0..3  -> cols warp_n*32 .. +31

    // Stage W1^T -> fp16 SW128 panels [n][k-quarter]
    for (int idx = tid; idx < HID * H2; idx += 512) {
        int k = idx >> 7;          // 0..255
        int n = idx & 127;         // 0..127
        __half h = __float2half_rn(W1[idx]);
        uint32_t sw = SWZ128((uint32_t)n * 128u + (uint32_t)(k & 63) * 2u);
        int p = k >> 6;
        *(__half*)(smem + SM_W + p * 16384 + sw) = h;
    }
    if (tid < 128) ((float2*)(smem + SM_BW))[tid] = make_float2(b1[tid], W2[tid]);
    if (tid == 0)  ((float*)(smem + SM_B2))[0] = b2[0];
    __syncthreads();

    const float bias2 = ((float*)(smem + SM_B2))[0];
    const float2* bw  = (const float2*)(smem + SM_BW);
    float* sred       = (float*)(smem + SM_SRED);

    // Per-lane ldmatrix address components
    const int amat = lane >> 3;                          // 0..3
    const int arow0 = warp_m * 32 + ((amat & 1) << 3) + (lane & 7);  // mb adds 16
    const uint32_t aoff0 = (uint32_t)arow0 * 128u;
    const uint32_t axor  = (uint32_t)(lane & 7) << 4;
    const uint32_t amk   = (uint32_t)(amat >> 1) << 4;

    const int bmat = lane >> 3;
    const uint32_t browb = (uint32_t)(warp_n * 32 + ((bmat >> 1) << 3) + (lane & 7)) * 128u; // nbp adds 16 rows
    const uint32_t bxor  = (uint32_t)(lane & 7) << 4;
    const uint32_t bmk   = (uint32_t)(bmat & 1) << 4;

    const float4* x4 = (const float4*)x;

    int t = blockIdx.x;
    if (t >= numTiles) return;

    // prefetch (t, q=0): 4 float4 per thread
    float4 v[4];
    {
        const int base = t * 128;
#pragma unroll
        for (int it = 0; it < 4; it++) {
            int f = (it << 9) + tid;
            int row = f >> 4, c4 = f & 15;
            int gn = base + row; if (gn >= N) gn = N - 1;
            v[it] = x4[(size_t)gn * 64 + c4];
        }
    }

    for (; t < numTiles; t += gridDim.x) {
        const int base = t * 128;
        float d[2][4][4];   // [mb m16][nb n8][frag]
#pragma unroll
        for (int i = 0; i < 2; i++)
#pragma unroll
            for (int j = 0; j < 4; j++)
#pragma unroll
                for (int kreg = 0; kreg < 4; kreg++) d[i][j][kreg] = 0.0f;

        for (int q = 0; q < 4; q++) {
            const uint32_t abase = sb + SM_A + (uint32_t)(q & 1) * 16384u;
            __syncthreads();   // previous user of this buffer (q-2) done

            // store v (quarter q) as fp16 into buffer
#pragma unroll
            for (int it = 0; it < 4; it++) {
                int f = (it << 9) + tid;
                int row = f >> 4, c4 = f & 15;
                float4 w = v[it];
                __half2 h0 = __float22half2_rn(make_float2(w.x, w.y));
                __half2 h1 = __float22half2_rn(make_float2(w.z, w.w));
                uint32_t sw = SWZ128((uint32_t)row * 128u + (uint32_t)c4 * 8u);
                uint2 hv;
                hv.x = *(uint32_t*)&h0; hv.y = *(uint32_t*)&h1;
                *(uint2*)(smem + (abase - sb) + sw) = hv;
            }
            __syncthreads();

            // prefetch next quarter (overlaps MMA below)
            {
                int nt = (q < 3) ? t : t + (int)gridDim.x;
                int nq = (q + 1) & 3;
                if (nt < numTiles) {
                    const int nbase = nt * 128;
#pragma unroll
                    for (int it = 0; it < 4; it++) {
                        int f = (it << 9) + tid;
                        int row = f >> 4, c4 = f & 15;
                        int gn = nbase + row; if (gn >= N) gn = N - 1;
                        v[it] = x4[(size_t)gn * 64 + nq * 16 + c4];
                    }
                }
            }

            // compute: 4 k-steps of 16 over this quarter
            const uint32_t wbase = sb + SM_W + (uint32_t)q * 16384u;
#pragma unroll
            for (int ks = 0; ks < 4; ks++) {
                const uint32_t kk = (uint32_t)ks * 32u;
                const uint32_t aterm = (kk + amk) ^ axor;
                const uint32_t bterm = (kk + bmk) ^ bxor;
                uint32_t ah[2][4];
#pragma unroll
                for (int mb = 0; mb < 2; mb++)
                    ldsm4(ah[mb], abase + aoff0 + (uint32_t)mb * 2048u + aterm);
#pragma unroll
                for (int nbp = 0; nbp < 2; nbp++) {
                    uint32_t bh[4];
                    ldsm4(bh, wbase + (uint32_t)nbp * 2048u + browb + bterm);
#pragma unroll
                    for (int mb = 0; mb < 2; mb++) {
                        mma16816(d[mb][nbp * 2],     ah[mb], bh[0], bh[1]);
                        mma16816(d[mb][nbp * 2 + 1], ah[mb], bh[2], bh[3]);
                    }
                }
            }
        }

        // Epilogue: lane covers rows {r0, r0+8} per mb, cols warp_n*32+nb*8+2*(lane%4)+j
        const int cbase = warp_n * 32 + 2 * (lane & 3);
#pragma unroll
        for (int mb = 0; mb < 2; mb++) {
            float s0 = 0.0f, s1 = 0.0f;
#pragma unroll
            for (int nb = 0; nb < 4; nb++) {
#pragma unroll
                for (int j = 0; j < 2; j++) {
                    float2 bwv = bw[cbase + nb * 8 + j];
                    s0 = fmaf(tanh_hw(d[mb][nb][j]     + bwv.x), bwv.y, s0);
                    s1 = fmaf(tanh_hw(d[mb][nb][2 + j] + bwv.x), bwv.y, s1);
                }
            }
            s0 += __shfl_xor_sync(0xffffffffu, s0, 1);
            s0 += __shfl_xor_sync(0xffffffffu, s0, 2);
            s1 += __shfl_xor_sync(0xffffffffu, s1, 1);
            s1 += __shfl_xor_sync(0xffffffffu, s1, 2);
            if ((lane & 3) == 0) {
                int r0 = warp_m * 32 + mb * 16 + (lane >> 2);
                sred[r0 * 5 + warp_n]       = s0;
                sred[(r0 + 8) * 5 + warp_n] = s1;
            }
        }
        __syncthreads();
        if (tid < 128) {
            int gn = base + tid;
            if (gn < N) {
                float s = (sred[tid * 5 + 0] + sred[tid * 5 + 1]) +
                          (sred[tid * 5 + 2] + sred[tid * 5 + 3]);
                g_scores[gn] = s + bias2;
            }
        }
    }
}

// ---------------------------------------------------------------------------
// Batch dtype probe (JAX demotes int64->int32 unless x64 enabled)
// ---------------------------------------------------------------------------
__global__ void detect_kernel(const int* __restrict__ b32, int N)
{
    bool is64 = true;
    int checked = 0;
    for (int i = 1; i < 256 && checked < 16; i++) {
        int idx = N - i;
        if (idx < 1) break;
        if (idx & 1) {
            checked++;
            if (b32[idx] != 0) { is64 = false; break; }
        }
    }
    g_batch_is64 = is64 ? 1 : 0;
}

// ---------------------------------------------------------------------------
// Graph range offsets: batch sorted -> per-graph lower_bound
// ---------------------------------------------------------------------------
__global__ void offsets_kernel(const void* __restrict__ batch, int N, int G)
{
    int g = blockIdx.x * blockDim.x + threadIdx.x;
    if (g > G) return;
    if (g == G) { g_gstart[G] = N; return; }
    const int is64 = g_batch_is64;
    const long long* b64 = (const long long*)batch;
    const int*       b32 = (const int*)batch;
    int lo = 0, hi = N;
    while (lo < hi) {
        int mid = (lo + hi) >> 1;
        long long v = is64 ? b64[mid] : (long long)b32[mid];
        if (v < (long long)g) lo = mid + 1; else hi = mid;
    }
    g_gstart[g] = lo;
}

// ---------------------------------------------------------------------------
// Pass B+C fused: per-graph segment softmax + weighted feature sum (float4).
// ---------------------------------------------------------------------------
#define CHUNK 1024
__global__ __launch_bounds__(256)
void pool_kernel(const float4* __restrict__ x4, float4* __restrict__ out4)
{
    const int g   = blockIdx.x;
    const int tid = threadIdx.x;
    const int s = g_gstart[g], e = g_gstart[g + 1];

    __shared__ float  red[256];
    __shared__ float  wbuf[CHUNK];
    __shared__ float4 red4[256];

    // phase 1: segment max
    float m = -3.0e38f;
    for (int i = s + tid; i < e; i += 256) m = fmaxf(m, g_scores[i]);
    red[tid] = m; __syncthreads();
#pragma unroll
    for (int o = 128; o > 0; o >>= 1) {
        if (tid < o) red[tid] = fmaxf(red[tid], red[tid + o]);
        __syncthreads();
    }
    m = red[0]; __syncthreads();

    // phase 2: denom
    float dsum = 0.0f;
    for (int i = s + tid; i < e; i += 256) dsum += __expf(g_scores[i] - m);
    red[tid] = dsum; __syncthreads();
#pragma unroll
    for (int o = 128; o > 0; o >>= 1) {
        if (tid < o) red[tid] += red[tid + o];
        __syncthreads();
    }
    float inv = (e > s) ? (1.0f / red[0]) : 0.0f;
    __syncthreads();

    // phase 3: weighted sum, float4 per thread, 4 node groups
    const int c  = tid & 63;
    const int gr = tid >> 6;
    float4 acc = make_float4(0.f, 0.f, 0.f, 0.f);
    for (int cs = s; cs < e; cs += CHUNK) {
        int ce = min(e, cs + CHUNK);
        for (int i = cs + tid; i < ce; i += 256)
            wbuf[i - cs] = __expf(g_scores[i] - m) * inv;
        __syncthreads();
        int cnt = ce - cs;
#pragma unroll 2
        for (int i = gr; i < cnt; i += 4) {
            float w = wbuf[i];
            float4 vv = x4[(size_t)(cs + i) * 64 + c];
            acc.x = fmaf(vv.x, w, acc.x);
            acc.y = fmaf(vv.y, w, acc.y);
            acc.z = fmaf(vv.z, w, acc.z);
            acc.w = fmaf(vv.w, w, acc.w);
        }
        __syncthreads();
    }
    red4[tid] = acc;
    __syncthreads();
    if (tid < 64) {
        float4 a = red4[tid], b = red4[tid + 64], cc = red4[tid + 128], dd = red4[tid + 192];
        float4 r;
        r.x = (a.x + b.x) + (cc.x + dd.x);
        r.y = (a.y + b.y) + (cc.y + dd.y);
        r.z = (a.z + b.z) + (cc.z + dd.z);
        r.w = (a.w + b.w) + (cc.w + dd.w);
        out4[(size_t)g * 64 + tid] = r;
    }
}

// ---------------------------------------------------------------------------
extern "C" void kernel_launch(void* const* d_in, const int* in_sizes, int n_in,
                              void* d_out, int out_size)
{
    const float* x     = (const float*)d_in[0];
    const void*  batch = d_in[1];
    const float* W1    = (const float*)d_in[2];
    const float* b1    = (const float*)d_in[3];
    const float* W2    = (const float*)d_in[4];
    const float* b2    = (const float*)d_in[5];

    const int N = in_sizes[0] / HID;
    const int G = out_size / HID;
    const int numTiles = (N + 127) / 128;

    int dev = 0;
    cudaGetDevice(&dev);
    int sms = 148;
    if (cudaDeviceGetAttribute(&sms, cudaDevAttrMultiProcessorCount, dev) != cudaSuccess || sms <= 0)
        sms = 148;

    cudaFuncSetAttribute(scores_mma_kernel,
                         cudaFuncAttributeMaxDynamicSharedMemorySize, SM_TOTAL);

    detect_kernel<<<1, 1>>>((const int*)batch, N);
    offsets_kernel<<<(G + 1 + 255) / 256, 256>>>(batch, N, G);

    int grid = sms < numTiles ? sms : numTiles;
    scores_mma_kernel<<<grid, 512, SM_TOTAL>>>(x, W1, b1, W2, b2, N, numTiles);
    pool_kernel<<<G, 256>>>((const float4*)x, (float4*)d_out);
}